// round 8
// baseline (speedup 1.0000x reference)
#include <cuda_runtime.h>
#include <cuda_fp16.h>
#include <math.h>

#define NMAX 50000
#define EMAX 800000
#define NB1 148                  // build blocks (1/SM, co-resident)
#define BT1 1024
#define NT1 (NB1 * BT1)
#define NB2 592                  // gather blocks (4/SM via launch_bounds)

// ---------------- scratch (static device memory) ----------------
__device__ float  g_dinv[NMAX];
__device__ int    g_deg[NMAX];
__device__ int    g_off[NMAX + 1];
__device__ int    g_cur[NMAX];
__device__ volatile int g_pref[NB1];             // chained-scan prefixes (-1 = not ready)
__device__ int2   g_csr[EMAX];                   // .x = src, .y = weight bits
__device__ __half g_h1[(size_t)NMAX * 128];      // x @ W1 (fp16)
__device__ __half g_hr[(size_t)NMAX * 128];      // relu(agg1+b1) (fp16)
__device__ float  g_h2[(size_t)NMAX * 16];       // g_hr @ W2

// ---------------- software grid barrier (self-restoring across replays) ----------------
__device__ unsigned g_cnt[2] = {0, 0};
__device__ volatile unsigned g_gen[2] = {0, 0};

__device__ __forceinline__ void gbar(int which, unsigned nb) {
    __syncthreads();
    if (threadIdx.x == 0) {
        __threadfence();
        unsigned g = g_gen[which];
        if (atomicAdd(&g_cnt[which], 1u) == nb - 1u) {
            g_cnt[which] = 0u;
            __threadfence();
            g_gen[which] = g + 1u;
        } else {
            while (g_gen[which] == g) { }
            __threadfence();
        }
    }
    __syncthreads();
}

// ---------------- f32x2 packed math helpers ----------------
__device__ __forceinline__ unsigned long long pk2(float a, float b) {
    unsigned long long r;
    asm("mov.b64 %0, {%1, %2};" : "=l"(r) : "f"(a), "f"(b));
    return r;
}
__device__ __forceinline__ float2 up2(unsigned long long v) {
    float2 r;
    asm("mov.b64 {%0, %1}, %2;" : "=f"(r.x), "=f"(r.y) : "l"(v));
    return r;
}
__device__ __forceinline__ unsigned long long ffma2(unsigned long long a,
                                                    unsigned long long b,
                                                    unsigned long long c) {
    unsigned long long d;
    asm("fma.rn.f32x2 %0, %1, %2, %3;" : "=l"(d) : "l"(a), "l"(b), "l"(c));
    return d;
}

// ==================== fused CSR build: 3 grid barriers ====================
__global__ __launch_bounds__(BT1) void k_build(const int* __restrict__ ei, int n, int E) {
    __shared__ int s_is64;
    __shared__ int wsum[32];
    __shared__ int s_carry;
    __shared__ int s_base;
    int tid = threadIdx.x, lane = tid & 31, wid = tid >> 5;
    int b = blockIdx.x;
    int gtid = b * BT1 + tid;

    // ---- P0: dtype detect + zero degrees + reset chain sentinels ----
    {
        // int64 little-endian: odd words = zero high halves; int32: random ids.
        int v = ei[2 * gtid + 1];                 // gtid < NT1 < E
        int any = __syncthreads_or(v != 0);
        if (tid == 0) { s_is64 = any ? 0 : 1; g_pref[b] = -1; }
    }
    for (int i = gtid; i < n; i += NT1) g_deg[i] = 0;
    gbar(0, NB1);
    int is64 = s_is64;

    // ---- P1: in-degree count ----
    if (is64) {
        for (int e = gtid; e < E; e += NT1) atomicAdd(&g_deg[ei[2 * E + 2 * e]], 1);
    } else {
        for (int e = gtid; e < E; e += NT1) atomicAdd(&g_deg[ei[E + e]], 1);
    }
    gbar(0, NB1);

    // ---- P2: region scan + chained lookback + finalize (one phase) ----
    int chunk = (n + NB1 - 1) / NB1;
    int r0 = b * chunk;
    int r1 = min(r0 + chunk, n);
    if (tid == 0) s_carry = 0;
    __syncthreads();
    for (int t0 = r0; t0 < r1; t0 += BT1) {
        int i = t0 + tid;
        int deg = (i < r1) ? __ldcg(&g_deg[i]) : 0;
        int v = deg;
#pragma unroll
        for (int o = 1; o < 32; o <<= 1) {
            int t = __shfl_up_sync(0xffffffffu, v, o);
            if (lane >= o) v += t;
        }
        if (lane == 31) wsum[wid] = v;
        __syncthreads();
        if (wid == 0) {
            int s = wsum[lane];
#pragma unroll
            for (int o = 1; o < 32; o <<= 1) {
                int t = __shfl_up_sync(0xffffffffu, s, o);
                if (lane >= o) s += t;
            }
            wsum[lane] = s;
        }
        __syncthreads();
        int excl = s_carry + (wid ? wsum[wid - 1] : 0) + v - deg;
        if (i < r1) {
            g_off[i] = excl;                       // region-local
            g_dinv[i] = rsqrtf((float)deg + 1.0f);
        }
        __syncthreads();
        if (tid == 0) s_carry += wsum[31];
        __syncthreads();
    }
    if (tid == 0) {
        int prev = 0;
        if (b > 0) { while ((prev = g_pref[b - 1]) == -1) { } }
        __threadfence();
        g_pref[b] = prev + s_carry;                // publish inclusive prefix
        s_base = prev;
        if (b == NB1 - 1) g_off[n] = E;
    }
    __syncthreads();
    {
        int base = s_base;
        for (int i = r0 + tid; i < r1; i += BT1) {
            int o = g_off[i] + base;
            g_off[i] = o;
            g_cur[i] = o;
        }
    }
    gbar(0, NB1);

    // ---- P3: place edges (packed src + weight, one 8B store) ----
    if (is64) {
        for (int e = gtid; e < E; e += NT1) {
            int s = ei[2 * e], d = ei[2 * E + 2 * e];
            int slot = atomicAdd(&g_cur[d], 1);
            int2 p; p.x = s; p.y = __float_as_int(g_dinv[s] * g_dinv[d]);
            g_csr[slot] = p;
        }
    } else {
        for (int e = gtid; e < E; e += NT1) {
            int s = ei[e], d = ei[E + e];
            int slot = atomicAdd(&g_cur[d], 1);
            int2 p; p.x = s; p.y = __float_as_int(g_dinv[s] * g_dinv[d]);
            g_csr[slot] = p;
        }
    }
}

// ==================== GEMM1: h1 = x @ W1 -> fp16 store ====================
__global__ __launch_bounds__(128) void k_gemm1(const float* __restrict__ x,
                                               const float* __restrict__ W,
                                               int n) {
    __shared__ float ws[32][128];
    __shared__ float xs[32][68];
    int tid = threadIdx.x;
    int row0 = blockIdx.x * 64;
    int tr = tid >> 4;
    int tc = tid & 15;
    unsigned long long acc[8][4];
#pragma unroll
    for (int r = 0; r < 8; ++r)
#pragma unroll
        for (int j = 0; j < 4; ++j) acc[r][j] = 0ull;

    for (int kc = 0; kc < 4; ++kc) {
        __syncthreads();
        for (int i = tid * 4; i < 32 * 128; i += 128 * 4)
            *(float4*)(&ws[0][0] + i) = *(const float4*)(W + kc * 32 * 128 + i);
        for (int i = tid; i < 64 * 32; i += 128) {
            int r = i >> 5, k = i & 31;
            int gr = row0 + r;
            xs[k][r] = (gr < n) ? x[(size_t)gr * 128 + kc * 32 + k] : 0.0f;
        }
        __syncthreads();
#pragma unroll 4
        for (int k = 0; k < 32; ++k) {
            float4 xa = *(const float4*)&xs[k][tr * 8];
            float4 xb = *(const float4*)&xs[k][tr * 8 + 4];
            float4 wa = *(const float4*)&ws[k][tc * 8];
            float4 wb = *(const float4*)&ws[k][tc * 8 + 4];
            unsigned long long wp[4] = { pk2(wa.x, wa.y), pk2(wa.z, wa.w),
                                         pk2(wb.x, wb.y), pk2(wb.z, wb.w) };
            unsigned long long xd[8] = { pk2(xa.x, xa.x), pk2(xa.y, xa.y),
                                         pk2(xa.z, xa.z), pk2(xa.w, xa.w),
                                         pk2(xb.x, xb.x), pk2(xb.y, xb.y),
                                         pk2(xb.z, xb.z), pk2(xb.w, xb.w) };
#pragma unroll
            for (int r = 0; r < 8; ++r)
#pragma unroll
                for (int j = 0; j < 4; ++j)
                    acc[r][j] = ffma2(xd[r], wp[j], acc[r][j]);
        }
    }
#pragma unroll
    for (int r = 0; r < 8; ++r) {
        int gr = row0 + tr * 8 + r;
        if (gr >= n) continue;
        float2 p0 = up2(acc[r][0]), p1 = up2(acc[r][1]);
        float2 p2 = up2(acc[r][2]), p3 = up2(acc[r][3]);
        __half2 h[4] = { __float22half2_rn(p0), __float22half2_rn(p1),
                         __float22half2_rn(p2), __float22half2_rn(p3) };
        *(uint4*)(g_h1 + (size_t)gr * 128 + tc * 8) = *(const uint4*)h;
    }
}

// ==================== fused gathers: L1 -> bar -> GEMM2 -> bar -> L2 ====================
__device__ __forceinline__ void fma8(float* a, uint4 u, float w) {
    __half2* h = (__half2*)&u;
#pragma unroll
    for (int j = 0; j < 4; ++j) {
        float2 f = __half22float2(h[j]);
        a[2 * j]     += f.x * w;
        a[2 * j + 1] += f.y * w;
    }
}

__global__ __launch_bounds__(256, 4) void k_gather(float* __restrict__ out,
                                                   const float* __restrict__ b1,
                                                   const float* __restrict__ W2,
                                                   const float* __restrict__ b2,
                                                   int n) {
    __shared__ float w2t[16][128];    // transposed: w2t[c][k] = W2[k*16+c]
    int tid = threadIdx.x;
    for (int i = tid; i < 2048; i += 256) w2t[i & 15][i >> 4] = W2[i];
    __syncthreads();

    int warp = tid >> 5, lane = tid & 31;
    int half = lane >> 4, hl = lane & 15;
    int c = hl << 3;                  // 8 halfs (16 B) per lane
    int npair = (n + 1) >> 1;

    // ---- phase A: layer-1 aggregation + b1 + relu -> g_hr (fp16), half-warp/node ----
    for (int pair = blockIdx.x * 8 + warp; pair < npair; pair += NB2 * 8) {
        int node = pair * 2 + half;
        if (node >= n) continue;
        float a[8];
        float di = g_dinv[node];
        float w0 = di * di;
        uint4 u = *(const uint4*)(g_h1 + (size_t)node * 128 + c);
        {
            __half2* h = (__half2*)&u;
#pragma unroll
            for (int j = 0; j < 4; ++j) {
                float2 f = __half22float2(h[j]);
                a[2 * j]     = f.x * w0;
                a[2 * j + 1] = f.y * w0;
            }
        }
        int e = g_off[node], e1 = g_off[node + 1];
        for (; e + 4 <= e1; e += 4) {
            int2 p0 = g_csr[e],     p1 = g_csr[e + 1];
            int2 p2 = g_csr[e + 2], p3 = g_csr[e + 3];
            uint4 u0 = *(const uint4*)(g_h1 + (size_t)p0.x * 128 + c);
            uint4 u1 = *(const uint4*)(g_h1 + (size_t)p1.x * 128 + c);
            uint4 u2 = *(const uint4*)(g_h1 + (size_t)p2.x * 128 + c);
            uint4 u3 = *(const uint4*)(g_h1 + (size_t)p3.x * 128 + c);
            fma8(a, u0, __int_as_float(p0.y));
            fma8(a, u1, __int_as_float(p1.y));
            fma8(a, u2, __int_as_float(p2.y));
            fma8(a, u3, __int_as_float(p3.y));
        }
        for (; e < e1; ++e) {
            int2 p = g_csr[e];
            uint4 uu = *(const uint4*)(g_h1 + (size_t)p.x * 128 + c);
            fma8(a, uu, __int_as_float(p.y));
        }
        float4 ba = *(const float4*)(b1 + c);
        float4 bb = *(const float4*)(b1 + c + 4);
        float r0 = fmaxf(a[0] + ba.x, 0.0f), r1 = fmaxf(a[1] + ba.y, 0.0f);
        float r2 = fmaxf(a[2] + ba.z, 0.0f), r3 = fmaxf(a[3] + ba.w, 0.0f);
        float r4 = fmaxf(a[4] + bb.x, 0.0f), r5 = fmaxf(a[5] + bb.y, 0.0f);
        float r6 = fmaxf(a[6] + bb.z, 0.0f), r7 = fmaxf(a[7] + bb.w, 0.0f);
        uint4 o;
        __half2* hp = (__half2*)&o;
        hp[0] = __floats2half2_rn(r0, r1);
        hp[1] = __floats2half2_rn(r2, r3);
        hp[2] = __floats2half2_rn(r4, r5);
        hp[3] = __floats2half2_rn(r6, r7);
        *(uint4*)(g_hr + (size_t)node * 128 + c) = o;
    }

    gbar(1, NB2);

    // ---- phase B: GEMM2, thread per node, broadcast smem W2t ----
    for (int node = blockIdx.x * 256 + tid; node < n; node += NB2 * 256) {
        const __half* row = g_hr + (size_t)node * 128;
        float acc[16];
#pragma unroll
        for (int j = 0; j < 16; ++j) acc[j] = 0.0f;
#pragma unroll 4
        for (int kk = 0; kk < 16; ++kk) {
            uint4 u = *(const uint4*)(row + kk * 8);
            __half2* h = (__half2*)&u;
            float f[8];
#pragma unroll
            for (int j = 0; j < 4; ++j) {
                float2 t = __half22float2(h[j]);
                f[2 * j] = t.x; f[2 * j + 1] = t.y;
            }
#pragma unroll
            for (int j = 0; j < 2; ++j) {
                int k4 = kk * 8 + j * 4;
#pragma unroll
                for (int cc = 0; cc < 16; ++cc) {
                    float4 w = *(const float4*)&w2t[cc][k4];
                    acc[cc] += f[4 * j] * w.x + f[4 * j + 1] * w.y
                             + f[4 * j + 2] * w.z + f[4 * j + 3] * w.w;
                }
            }
        }
        float* dst = g_h2 + (size_t)node * 16;
#pragma unroll
        for (int j = 0; j < 4; ++j)
            *(float4*)(dst + 4 * j) = make_float4(acc[4*j], acc[4*j+1], acc[4*j+2], acc[4*j+3]);
    }

    gbar(1, NB2);

    // ---- phase C: layer-2 gather (4 lanes/node) + b2 + log_softmax ----
    for (int idx = blockIdx.x * 256 + tid; idx < n * 4; idx += NB2 * 256) {
        int node = idx >> 2;
        int q = (idx & 3) << 2;
        float di = g_dinv[node];
        float w0 = di * di;
        float4 acc = *(const float4*)(g_h2 + (size_t)node * 16 + q);
        acc.x *= w0; acc.y *= w0; acc.z *= w0; acc.w *= w0;
        int e = g_off[node], e1 = g_off[node + 1];
        for (; e + 4 <= e1; e += 4) {
            int2 p0 = g_csr[e],     p1 = g_csr[e + 1];
            int2 p2 = g_csr[e + 2], p3 = g_csr[e + 3];
            float4 v0 = *(const float4*)(g_h2 + (size_t)p0.x * 16 + q);
            float4 v1 = *(const float4*)(g_h2 + (size_t)p1.x * 16 + q);
            float4 v2 = *(const float4*)(g_h2 + (size_t)p2.x * 16 + q);
            float4 v3 = *(const float4*)(g_h2 + (size_t)p3.x * 16 + q);
            float w0_ = __int_as_float(p0.y), w1_ = __int_as_float(p1.y);
            float w2_ = __int_as_float(p2.y), w3_ = __int_as_float(p3.y);
            acc.x += v0.x * w0_ + v1.x * w1_ + v2.x * w2_ + v3.x * w3_;
            acc.y += v0.y * w0_ + v1.y * w1_ + v2.y * w2_ + v3.y * w3_;
            acc.z += v0.z * w0_ + v1.z * w1_ + v2.z * w2_ + v3.z * w3_;
            acc.w += v0.w * w0_ + v1.w * w1_ + v2.w * w2_ + v3.w * w3_;
        }
        for (; e < e1; ++e) {
            int2 p = g_csr[e];
            float wt = __int_as_float(p.y);
            float4 v = *(const float4*)(g_h2 + (size_t)p.x * 16 + q);
            acc.x += v.x * wt; acc.y += v.y * wt; acc.z += v.z * wt; acc.w += v.w * wt;
        }
        float4 b = *(const float4*)(b2 + q);
        float4 v = make_float4(acc.x + b.x, acc.y + b.y, acc.z + b.z, acc.w + b.w);
        float m = fmaxf(fmaxf(v.x, v.y), fmaxf(v.z, v.w));
        m = fmaxf(m, __shfl_xor_sync(0xffffffffu, m, 1, 4));
        m = fmaxf(m, __shfl_xor_sync(0xffffffffu, m, 2, 4));
        float s4 = expf(v.x - m) + expf(v.y - m) + expf(v.z - m) + expf(v.w - m);
        s4 += __shfl_xor_sync(0xffffffffu, s4, 1, 4);
        s4 += __shfl_xor_sync(0xffffffffu, s4, 2, 4);
        float L = m + logf(s4);
        *(float4*)(out + (size_t)node * 16 + q) =
            make_float4(v.x - L, v.y - L, v.z - L, v.w - L);
    }
}

// ---------------- launch: fork/join, fused build || gemm1, then fused gather ----------------
extern "C" void kernel_launch(void* const* d_in, const int* in_sizes, int n_in,
                              void* d_out, int out_size) {
    const float* x  = (const float*)d_in[0];
    const int*   ei = (const int*)d_in[1];
    const float* W1 = (const float*)d_in[2];
    const float* b1 = (const float*)d_in[3];
    const float* W2 = (const float*)d_in[4];
    const float* b2 = (const float*)d_in[5];
    float* out = (float*)d_out;

    int n = in_sizes[0] / 128;
    int E = in_sizes[1] / 2;

    static cudaStream_t s1 = nullptr, s2 = nullptr;
    static cudaEvent_t ev0 = nullptr, ev1 = nullptr, ev2 = nullptr;
    if (!s1) {
        cudaStreamCreateWithFlags(&s1, cudaStreamNonBlocking);
        cudaStreamCreateWithFlags(&s2, cudaStreamNonBlocking);
        cudaEventCreateWithFlags(&ev0, cudaEventDisableTiming);
        cudaEventCreateWithFlags(&ev1, cudaEventDisableTiming);
        cudaEventCreateWithFlags(&ev2, cudaEventDisableTiming);
    }

    cudaEventRecord(ev0, 0);
    cudaStreamWaitEvent(s1, ev0, 0);
    cudaStreamWaitEvent(s2, ev0, 0);

    k_build<<<NB1, BT1, 0, s1>>>(ei, n, E);
    cudaEventRecord(ev1, s1);

    k_gemm1<<<(n + 63) / 64, 128, 0, s2>>>(x, W1, n);
    cudaEventRecord(ev2, s2);

    cudaStreamWaitEvent(0, ev1, 0);
    cudaStreamWaitEvent(0, ev2, 0);

    k_gather<<<NB2, 256>>>(out, b1, W2, b2, n);
}

// round 9
// speedup vs baseline: 1.0454x; 1.0454x over previous
#include <cuda_runtime.h>
#include <cuda_fp16.h>
#include <math.h>

#define NMAX 50000
#define EMAX 800000
#define NB1 148                  // build blocks (1/SM, co-resident)
#define BT1 1024
#define NT1 (NB1 * BT1)
#define NB2 592                  // gather blocks (4/SM via launch_bounds)

// ---------------- scratch (static device memory) ----------------
__device__ float  g_dinv[NMAX];
__device__ int    g_deg[NMAX];
__device__ int    g_off[NMAX + 1];
__device__ int    g_cur[NMAX];
__device__ int    g_bsum[NB1 + 8];
__device__ int2   g_csr[EMAX];                   // .x = src, .y = weight bits
__device__ __half g_h1[(size_t)NMAX * 128];      // x @ W1 (fp16)
__device__ __half g_hr[(size_t)NMAX * 128];      // relu(agg1+b1) (fp16)
__device__ float  g_h2[(size_t)NMAX * 16];       // g_hr @ W2

// ---------------- software grid barrier (nanosleep backoff, self-restoring) ----------------
__device__ unsigned g_cnt[2] = {0, 0};
__device__ volatile unsigned g_gen[2] = {0, 0};

__device__ __forceinline__ void gbar(int which, unsigned nb) {
    __syncthreads();
    if (threadIdx.x == 0) {
        __threadfence();
        unsigned g = g_gen[which];
        if (atomicAdd(&g_cnt[which], 1u) == nb - 1u) {
            g_cnt[which] = 0u;
            __threadfence();
            g_gen[which] = g + 1u;
        } else {
            while (g_gen[which] == g) __nanosleep(64);
        }
    }
    __syncthreads();
}

// ---------------- f32x2 packed math helpers ----------------
__device__ __forceinline__ unsigned long long pk2(float a, float b) {
    unsigned long long r;
    asm("mov.b64 %0, {%1, %2};" : "=l"(r) : "f"(a), "f"(b));
    return r;
}
__device__ __forceinline__ float2 up2(unsigned long long v) {
    float2 r;
    asm("mov.b64 {%0, %1}, %2;" : "=f"(r.x), "=f"(r.y) : "l"(v));
    return r;
}
__device__ __forceinline__ unsigned long long ffma2(unsigned long long a,
                                                    unsigned long long b,
                                                    unsigned long long c) {
    unsigned long long d;
    asm("fma.rn.f32x2 %0, %1, %2, %3;" : "=l"(d) : "l"(a), "l"(b), "l"(c));
    return d;
}

// ==================== fused CSR build (R7 proven version: 5 phases) ====================
__global__ __launch_bounds__(BT1) void k_build(const int* __restrict__ ei, int n, int E) {
    __shared__ int s_is64;
    __shared__ int wsum[32];
    __shared__ int s_carry;
    int tid = threadIdx.x, lane = tid & 31, wid = tid >> 5;
    int b = blockIdx.x;
    int gtid = b * BT1 + tid;

    // ---- P0: dtype detect (per-block sample) + zero degrees ----
    {
        // int64 little-endian: odd words = zero high halves; int32: random ids.
        int v = ei[2 * gtid + 1];                 // gtid < NT1 <= 2E, in-bounds both dtypes
        int any = __syncthreads_or(v != 0);
        if (tid == 0) s_is64 = any ? 0 : 1;
    }
    for (int i = gtid; i < n; i += NT1) g_deg[i] = 0;
    gbar(0, NB1);
    int is64 = s_is64;

    // ---- P1: in-degree count ----
    if (is64) {
        for (int e = gtid; e < E; e += NT1) atomicAdd(&g_deg[ei[2 * E + 2 * e]], 1);
    } else {
        for (int e = gtid; e < E; e += NT1) atomicAdd(&g_deg[ei[E + e]], 1);
    }
    gbar(0, NB1);

    // ---- P2: per-block local exclusive scan over contiguous region (+ dinv) ----
    int chunk = (n + NB1 - 1) / NB1;
    int r0 = b * chunk;
    int r1 = min(r0 + chunk, n);
    if (tid == 0) s_carry = 0;
    __syncthreads();
    for (int t0 = r0; t0 < r1; t0 += BT1) {
        int i = t0 + tid;
        int deg = (i < r1) ? __ldcg(&g_deg[i]) : 0;
        int v = deg;
#pragma unroll
        for (int o = 1; o < 32; o <<= 1) {
            int t = __shfl_up_sync(0xffffffffu, v, o);
            if (lane >= o) v += t;
        }
        if (lane == 31) wsum[wid] = v;
        __syncthreads();
        if (wid == 0) {
            int s = wsum[lane];
#pragma unroll
            for (int o = 1; o < 32; o <<= 1) {
                int t = __shfl_up_sync(0xffffffffu, s, o);
                if (lane >= o) s += t;
            }
            wsum[lane] = s;
        }
        __syncthreads();
        int excl = s_carry + (wid ? wsum[wid - 1] : 0) + v - deg;
        if (i < r1) {
            g_off[i] = excl;                       // region-local
            g_dinv[i] = rsqrtf((float)deg + 1.0f);
        }
        __syncthreads();
        if (tid == 0) s_carry += wsum[31];
        __syncthreads();
    }
    if (tid == 0) g_bsum[b] = s_carry;
    gbar(0, NB1);

    // ---- P3: block 0 exclusive-scans the NB1 region totals (parallel, no chain) ----
    if (b == 0) {
        int v = (tid < NB1) ? __ldcg(&g_bsum[tid]) : 0;
        int x = v;
#pragma unroll
        for (int o = 1; o < 32; o <<= 1) {
            int t = __shfl_up_sync(0xffffffffu, x, o);
            if (lane >= o) x += t;
        }
        if (lane == 31) wsum[wid] = x;
        __syncthreads();
        if (wid == 0) {
            int s = wsum[lane];
#pragma unroll
            for (int o = 1; o < 32; o <<= 1) {
                int t = __shfl_up_sync(0xffffffffu, s, o);
                if (lane >= o) s += t;
            }
            wsum[lane] = s;
        }
        __syncthreads();
        if (tid < NB1) g_bsum[tid] = (wid ? wsum[wid - 1] : 0) + x - v;
    }
    gbar(0, NB1);

    // ---- P4: add region base -> final offsets + cursors ----
    {
        int base = __ldcg(&g_bsum[b]);
        for (int i = r0 + tid; i < r1; i += BT1) {
            int o = g_off[i] + base;
            g_off[i] = o;
            g_cur[i] = o;
        }
        if (gtid == 0) g_off[n] = E;
    }
    gbar(0, NB1);

    // ---- P5: place edges (packed src + weight, one 8B store) ----
    if (is64) {
        for (int e = gtid; e < E; e += NT1) {
            int s = ei[2 * e], d = ei[2 * E + 2 * e];
            int slot = atomicAdd(&g_cur[d], 1);
            int2 p; p.x = s; p.y = __float_as_int(g_dinv[s] * g_dinv[d]);
            g_csr[slot] = p;
        }
    } else {
        for (int e = gtid; e < E; e += NT1) {
            int s = ei[e], d = ei[E + e];
            int slot = atomicAdd(&g_cur[d], 1);
            int2 p; p.x = s; p.y = __float_as_int(g_dinv[s] * g_dinv[d]);
            g_csr[slot] = p;
        }
    }
}

// ==================== GEMM1: h1 = x @ W1 -> fp16 store ====================
__global__ __launch_bounds__(128) void k_gemm1(const float* __restrict__ x,
                                               const float* __restrict__ W,
                                               int n) {
    __shared__ float ws[32][128];
    __shared__ float xs[32][68];
    int tid = threadIdx.x;
    int row0 = blockIdx.x * 64;
    int tr = tid >> 4;
    int tc = tid & 15;
    unsigned long long acc[8][4];
#pragma unroll
    for (int r = 0; r < 8; ++r)
#pragma unroll
        for (int j = 0; j < 4; ++j) acc[r][j] = 0ull;

    for (int kc = 0; kc < 4; ++kc) {
        __syncthreads();
        for (int i = tid * 4; i < 32 * 128; i += 128 * 4)
            *(float4*)(&ws[0][0] + i) = *(const float4*)(W + kc * 32 * 128 + i);
        for (int i = tid; i < 64 * 32; i += 128) {
            int r = i >> 5, k = i & 31;
            int gr = row0 + r;
            xs[k][r] = (gr < n) ? x[(size_t)gr * 128 + kc * 32 + k] : 0.0f;
        }
        __syncthreads();
#pragma unroll 4
        for (int k = 0; k < 32; ++k) {
            float4 xa = *(const float4*)&xs[k][tr * 8];
            float4 xb = *(const float4*)&xs[k][tr * 8 + 4];
            float4 wa = *(const float4*)&ws[k][tc * 8];
            float4 wb = *(const float4*)&ws[k][tc * 8 + 4];
            unsigned long long wp[4] = { pk2(wa.x, wa.y), pk2(wa.z, wa.w),
                                         pk2(wb.x, wb.y), pk2(wb.z, wb.w) };
            unsigned long long xd[8] = { pk2(xa.x, xa.x), pk2(xa.y, xa.y),
                                         pk2(xa.z, xa.z), pk2(xa.w, xa.w),
                                         pk2(xb.x, xb.x), pk2(xb.y, xb.y),
                                         pk2(xb.z, xb.z), pk2(xb.w, xb.w) };
#pragma unroll
            for (int r = 0; r < 8; ++r)
#pragma unroll
                for (int j = 0; j < 4; ++j)
                    acc[r][j] = ffma2(xd[r], wp[j], acc[r][j]);
        }
    }
#pragma unroll
    for (int r = 0; r < 8; ++r) {
        int gr = row0 + tr * 8 + r;
        if (gr >= n) continue;
        float2 p0 = up2(acc[r][0]), p1 = up2(acc[r][1]);
        float2 p2 = up2(acc[r][2]), p3 = up2(acc[r][3]);
        __half2 h[4] = { __float22half2_rn(p0), __float22half2_rn(p1),
                         __float22half2_rn(p2), __float22half2_rn(p3) };
        *(uint4*)(g_h1 + (size_t)gr * 128 + tc * 8) = *(const uint4*)h;
    }
}

// ==================== fused gathers: L1 -> bar -> GEMM2 -> bar -> L2 ====================
__device__ __forceinline__ void fma8(float* a, uint4 u, float w) {
    __half2* h = (__half2*)&u;
#pragma unroll
    for (int j = 0; j < 4; ++j) {
        float2 f = __half22float2(h[j]);
        a[2 * j]     += f.x * w;
        a[2 * j + 1] += f.y * w;
    }
}

__global__ __launch_bounds__(256, 4) void k_gather(float* __restrict__ out,
                                                   const float* __restrict__ b1,
                                                   const float* __restrict__ W2,
                                                   const float* __restrict__ b2,
                                                   int n) {
    __shared__ float w2t[16][128];    // transposed: w2t[c][k] = W2[k*16+c]
    int tid = threadIdx.x;
    for (int i = tid; i < 2048; i += 256) w2t[i & 15][i >> 4] = W2[i];
    __syncthreads();

    int warp = tid >> 5, lane = tid & 31;
    int half = lane >> 4, hl = lane & 15;
    int c = hl << 3;                  // 8 halfs (16 B) per lane
    int npair = (n + 1) >> 1;

    // ---- phase A: layer-1 aggregation + b1 + relu -> g_hr (fp16), half-warp/node ----
    for (int pair = blockIdx.x * 8 + warp; pair < npair; pair += NB2 * 8) {
        int node = pair * 2 + half;
        if (node >= n) continue;
        float a[8];
        float di = g_dinv[node];
        float w0 = di * di;
        uint4 u = *(const uint4*)(g_h1 + (size_t)node * 128 + c);
        {
            __half2* h = (__half2*)&u;
#pragma unroll
            for (int j = 0; j < 4; ++j) {
                float2 f = __half22float2(h[j]);
                a[2 * j]     = f.x * w0;
                a[2 * j + 1] = f.y * w0;
            }
        }
        int e = g_off[node], e1 = g_off[node + 1];
        for (; e + 4 <= e1; e += 4) {
            int2 p0 = g_csr[e],     p1 = g_csr[e + 1];
            int2 p2 = g_csr[e + 2], p3 = g_csr[e + 3];
            uint4 u0 = *(const uint4*)(g_h1 + (size_t)p0.x * 128 + c);
            uint4 u1 = *(const uint4*)(g_h1 + (size_t)p1.x * 128 + c);
            uint4 u2 = *(const uint4*)(g_h1 + (size_t)p2.x * 128 + c);
            uint4 u3 = *(const uint4*)(g_h1 + (size_t)p3.x * 128 + c);
            fma8(a, u0, __int_as_float(p0.y));
            fma8(a, u1, __int_as_float(p1.y));
            fma8(a, u2, __int_as_float(p2.y));
            fma8(a, u3, __int_as_float(p3.y));
        }
        for (; e < e1; ++e) {
            int2 p = g_csr[e];
            uint4 uu = *(const uint4*)(g_h1 + (size_t)p.x * 128 + c);
            fma8(a, uu, __int_as_float(p.y));
        }
        float4 ba = *(const float4*)(b1 + c);
        float4 bb = *(const float4*)(b1 + c + 4);
        float r0 = fmaxf(a[0] + ba.x, 0.0f), r1 = fmaxf(a[1] + ba.y, 0.0f);
        float r2 = fmaxf(a[2] + ba.z, 0.0f), r3 = fmaxf(a[3] + ba.w, 0.0f);
        float r4 = fmaxf(a[4] + bb.x, 0.0f), r5 = fmaxf(a[5] + bb.y, 0.0f);
        float r6 = fmaxf(a[6] + bb.z, 0.0f), r7 = fmaxf(a[7] + bb.w, 0.0f);
        uint4 o;
        __half2* hp = (__half2*)&o;
        hp[0] = __floats2half2_rn(r0, r1);
        hp[1] = __floats2half2_rn(r2, r3);
        hp[2] = __floats2half2_rn(r4, r5);
        hp[3] = __floats2half2_rn(r6, r7);
        *(uint4*)(g_hr + (size_t)node * 128 + c) = o;
    }

    gbar(1, NB2);

    // ---- phase B: GEMM2, thread per node, broadcast smem W2t ----
    for (int node = blockIdx.x * 256 + tid; node < n; node += NB2 * 256) {
        const __half* row = g_hr + (size_t)node * 128;
        float acc[16];
#pragma unroll
        for (int j = 0; j < 16; ++j) acc[j] = 0.0f;
#pragma unroll 4
        for (int kk = 0; kk < 16; ++kk) {
            uint4 u = *(const uint4*)(row + kk * 8);
            __half2* h = (__half2*)&u;
            float f[8];
#pragma unroll
            for (int j = 0; j < 4; ++j) {
                float2 t = __half22float2(h[j]);
                f[2 * j] = t.x; f[2 * j + 1] = t.y;
            }
#pragma unroll
            for (int j = 0; j < 2; ++j) {
                int k4 = kk * 8 + j * 4;
#pragma unroll
                for (int cc = 0; cc < 16; ++cc) {
                    float4 w = *(const float4*)&w2t[cc][k4];
                    acc[cc] += f[4 * j] * w.x + f[4 * j + 1] * w.y
                             + f[4 * j + 2] * w.z + f[4 * j + 3] * w.w;
                }
            }
        }
        float* dst = g_h2 + (size_t)node * 16;
#pragma unroll
        for (int j = 0; j < 4; ++j)
            *(float4*)(dst + 4 * j) = make_float4(acc[4*j], acc[4*j+1], acc[4*j+2], acc[4*j+3]);
    }

    gbar(1, NB2);

    // ---- phase C: layer-2 gather (4 lanes/node) + b2 + log_softmax ----
    for (int idx = blockIdx.x * 256 + tid; idx < n * 4; idx += NB2 * 256) {
        int node = idx >> 2;
        int q = (idx & 3) << 2;
        float di = g_dinv[node];
        float w0 = di * di;
        float4 acc = *(const float4*)(g_h2 + (size_t)node * 16 + q);
        acc.x *= w0; acc.y *= w0; acc.z *= w0; acc.w *= w0;
        int e = g_off[node], e1 = g_off[node + 1];
        for (; e + 4 <= e1; e += 4) {
            int2 p0 = g_csr[e],     p1 = g_csr[e + 1];
            int2 p2 = g_csr[e + 2], p3 = g_csr[e + 3];
            float4 v0 = *(const float4*)(g_h2 + (size_t)p0.x * 16 + q);
            float4 v1 = *(const float4*)(g_h2 + (size_t)p1.x * 16 + q);
            float4 v2 = *(const float4*)(g_h2 + (size_t)p2.x * 16 + q);
            float4 v3 = *(const float4*)(g_h2 + (size_t)p3.x * 16 + q);
            float w0_ = __int_as_float(p0.y), w1_ = __int_as_float(p1.y);
            float w2_ = __int_as_float(p2.y), w3_ = __int_as_float(p3.y);
            acc.x += v0.x * w0_ + v1.x * w1_ + v2.x * w2_ + v3.x * w3_;
            acc.y += v0.y * w0_ + v1.y * w1_ + v2.y * w2_ + v3.y * w3_;
            acc.z += v0.z * w0_ + v1.z * w1_ + v2.z * w2_ + v3.z * w3_;
            acc.w += v0.w * w0_ + v1.w * w1_ + v2.w * w2_ + v3.w * w3_;
        }
        for (; e < e1; ++e) {
            int2 p = g_csr[e];
            float wt = __int_as_float(p.y);
            float4 v = *(const float4*)(g_h2 + (size_t)p.x * 16 + q);
            acc.x += v.x * wt; acc.y += v.y * wt; acc.z += v.z * wt; acc.w += v.w * wt;
        }
        float4 b = *(const float4*)(b2 + q);
        float4 v = make_float4(acc.x + b.x, acc.y + b.y, acc.z + b.z, acc.w + b.w);
        float m = fmaxf(fmaxf(v.x, v.y), fmaxf(v.z, v.w));
        m = fmaxf(m, __shfl_xor_sync(0xffffffffu, m, 1, 4));
        m = fmaxf(m, __shfl_xor_sync(0xffffffffu, m, 2, 4));
        float s4 = expf(v.x - m) + expf(v.y - m) + expf(v.z - m) + expf(v.w - m);
        s4 += __shfl_xor_sync(0xffffffffu, s4, 1, 4);
        s4 += __shfl_xor_sync(0xffffffffu, s4, 2, 4);
        float L = m + logf(s4);
        *(float4*)(out + (size_t)node * 16 + q) =
            make_float4(v.x - L, v.y - L, v.z - L, v.w - L);
    }
}

// ---------------- launch: fork/join, fused build || gemm1, then fused gather ----------------
extern "C" void kernel_launch(void* const* d_in, const int* in_sizes, int n_in,
                              void* d_out, int out_size) {
    const float* x  = (const float*)d_in[0];
    const int*   ei = (const int*)d_in[1];
    const float* W1 = (const float*)d_in[2];
    const float* b1 = (const float*)d_in[3];
    const float* W2 = (const float*)d_in[4];
    const float* b2 = (const float*)d_in[5];
    float* out = (float*)d_out;

    int n = in_sizes[0] / 128;
    int E = in_sizes[1] / 2;

    static cudaStream_t s1 = nullptr, s2 = nullptr;
    static cudaEvent_t ev0 = nullptr, ev1 = nullptr, ev2 = nullptr;
    if (!s1) {
        cudaStreamCreateWithFlags(&s1, cudaStreamNonBlocking);
        cudaStreamCreateWithFlags(&s2, cudaStreamNonBlocking);
        cudaEventCreateWithFlags(&ev0, cudaEventDisableTiming);
        cudaEventCreateWithFlags(&ev1, cudaEventDisableTiming);
        cudaEventCreateWithFlags(&ev2, cudaEventDisableTiming);
    }

    cudaEventRecord(ev0, 0);
    cudaStreamWaitEvent(s1, ev0, 0);
    cudaStreamWaitEvent(s2, ev0, 0);

    k_build<<<NB1, BT1, 0, s1>>>(ei, n, E);
    cudaEventRecord(ev1, s1);

    k_gemm1<<<(n + 63) / 64, 128, 0, s2>>>(x, W1, n);
    cudaEventRecord(ev2, s2);

    cudaStreamWaitEvent(0, ev1, 0);
    cudaStreamWaitEvent(0, ev2, 0);

    k_gather<<<NB2, 256>>>(out, b1, W2, b2, n);
}

// round 12
// speedup vs baseline: 1.8091x; 1.7305x over previous
#include <cuda_runtime.h>
#include <cuda_fp16.h>
#include <math.h>

#define NMAX 50000
#define EMAX 800000
#define NB1 148                  // build blocks (1/SM, co-resident)
#define BT1 1024
#define NT1 (NB1 * BT1)
#define NB2 592                  // gather blocks (4/SM via launch_bounds)

// ---------------- scratch (static device memory) ----------------
__device__ float  g_dinv[NMAX];
__device__ int    g_deg[NMAX];
__device__ int    g_off[NMAX + 1];
__device__ int    g_cur[NMAX];
__device__ int    g_bsum[NB1 + 8];
__device__ int2   g_csr[EMAX];                   // .x = src, .y = weight bits
__device__ __half g_h1[(size_t)NMAX * 128];      // x @ W1 (fp16)
__device__ float  g_h2[(size_t)NMAX * 16];       // relu(agg1+b1) @ W2

// ---------------- software grid barrier (nanosleep backoff, self-restoring) ----------------
__device__ unsigned g_cnt[2] = {0, 0};
__device__ volatile unsigned g_gen[2] = {0, 0};

__device__ __forceinline__ void gbar(int which, unsigned nb) {
    __syncthreads();
    if (threadIdx.x == 0) {
        __threadfence();
        unsigned g = g_gen[which];
        if (atomicAdd(&g_cnt[which], 1u) == nb - 1u) {
            g_cnt[which] = 0u;
            __threadfence();
            g_gen[which] = g + 1u;
        } else {
            while (g_gen[which] == g) __nanosleep(64);
        }
    }
    __syncthreads();
}

// ---------------- f32x2 packed math helpers ----------------
__device__ __forceinline__ unsigned long long pk2(float a, float b) {
    unsigned long long r;
    asm("mov.b64 %0, {%1, %2};" : "=l"(r) : "f"(a), "f"(b));
    return r;
}
__device__ __forceinline__ float2 up2(unsigned long long v) {
    float2 r;
    asm("mov.b64 {%0, %1}, %2;" : "=f"(r.x), "=f"(r.y) : "l"(v));
    return r;
}
__device__ __forceinline__ unsigned long long ffma2(unsigned long long a,
                                                    unsigned long long b,
                                                    unsigned long long c) {
    unsigned long long d;
    asm("fma.rn.f32x2 %0, %1, %2, %3;" : "=l"(d) : "l"(a), "l"(b), "l"(c));
    return d;
}

// ==================== fused CSR build (R7 5-phase + unrolled atomic MLP) ====================
__global__ __launch_bounds__(BT1) void k_build(const int* __restrict__ ei, int n, int E) {
    __shared__ int s_is64;
    __shared__ int wsum[32];
    __shared__ int s_carry;
    int tid = threadIdx.x, lane = tid & 31, wid = tid >> 5;
    int b = blockIdx.x;
    int gtid = b * BT1 + tid;

    // ---- P0: dtype detect (per-block sample) + zero degrees ----
    {
        // int64 little-endian: odd words = zero high halves; int32: random ids.
        int v = ei[2 * gtid + 1];                 // gtid < NT1 <= 2E, in-bounds both dtypes
        int any = __syncthreads_or(v != 0);
        if (tid == 0) s_is64 = any ? 0 : 1;
    }
    for (int i = gtid; i < n; i += NT1) g_deg[i] = 0;
    gbar(0, NB1);
    int is64 = s_is64;

    // ---- P1: in-degree count (unrolled x4, independent REDs) ----
    {
        int e0 = gtid;
        for (; e0 + 3 * NT1 < E; e0 += 4 * NT1) {
            int d0 = is64 ? ei[2 * E + 2 * e0]             : ei[E + e0];
            int d1 = is64 ? ei[2 * E + 2 * (e0 + NT1)]     : ei[E + e0 + NT1];
            int d2 = is64 ? ei[2 * E + 2 * (e0 + 2 * NT1)] : ei[E + e0 + 2 * NT1];
            int d3 = is64 ? ei[2 * E + 2 * (e0 + 3 * NT1)] : ei[E + e0 + 3 * NT1];
            atomicAdd(&g_deg[d0], 1);
            atomicAdd(&g_deg[d1], 1);
            atomicAdd(&g_deg[d2], 1);
            atomicAdd(&g_deg[d3], 1);
        }
        for (; e0 < E; e0 += NT1) {
            int d = is64 ? ei[2 * E + 2 * e0] : ei[E + e0];
            atomicAdd(&g_deg[d], 1);
        }
    }
    gbar(0, NB1);

    // ---- P2: per-block local exclusive scan over contiguous region (+ dinv) ----
    int chunk = (n + NB1 - 1) / NB1;
    int r0 = b * chunk;
    int r1 = min(r0 + chunk, n);
    if (tid == 0) s_carry = 0;
    __syncthreads();
    for (int t0 = r0; t0 < r1; t0 += BT1) {
        int i = t0 + tid;
        int deg = (i < r1) ? __ldcg(&g_deg[i]) : 0;
        int v = deg;
#pragma unroll
        for (int o = 1; o < 32; o <<= 1) {
            int t = __shfl_up_sync(0xffffffffu, v, o);
            if (lane >= o) v += t;
        }
        if (lane == 31) wsum[wid] = v;
        __syncthreads();
        if (wid == 0) {
            int s = wsum[lane];
#pragma unroll
            for (int o = 1; o < 32; o <<= 1) {
                int t = __shfl_up_sync(0xffffffffu, s, o);
                if (lane >= o) s += t;
            }
            wsum[lane] = s;
        }
        __syncthreads();
        int excl = s_carry + (wid ? wsum[wid - 1] : 0) + v - deg;
        if (i < r1) {
            g_off[i] = excl;                       // region-local
            g_dinv[i] = rsqrtf((float)deg + 1.0f);
        }
        __syncthreads();
        if (tid == 0) s_carry += wsum[31];
        __syncthreads();
    }
    if (tid == 0) g_bsum[b] = s_carry;
    gbar(0, NB1);

    // ---- P3: block 0 exclusive-scans the NB1 region totals (parallel) ----
    if (b == 0) {
        int v = (tid < NB1) ? __ldcg(&g_bsum[tid]) : 0;
        int x = v;
#pragma unroll
        for (int o = 1; o < 32; o <<= 1) {
            int t = __shfl_up_sync(0xffffffffu, x, o);
            if (lane >= o) x += t;
        }
        if (lane == 31) wsum[wid] = x;
        __syncthreads();
        if (wid == 0) {
            int s = wsum[lane];
#pragma unroll
            for (int o = 1; o < 32; o <<= 1) {
                int t = __shfl_up_sync(0xffffffffu, s, o);
                if (lane >= o) s += t;
            }
            wsum[lane] = s;
        }
        __syncthreads();
        if (tid < NB1) g_bsum[tid] = (wid ? wsum[wid - 1] : 0) + x - v;
    }
    gbar(0, NB1);

    // ---- P4: add region base -> final offsets + cursors ----
    {
        int base = __ldcg(&g_bsum[b]);
        for (int i = r0 + tid; i < r1; i += BT1) {
            int o = g_off[i] + base;
            g_off[i] = o;
            g_cur[i] = o;
        }
        if (gtid == 0) g_off[n] = E;
    }
    gbar(0, NB1);

    // ---- P5: place edges, unrolled x4 (independent slot atomics -> MLP=4) ----
    {
        int e0 = gtid;
        for (; e0 + 3 * NT1 < E; e0 += 4 * NT1) {
            int ea = e0, eb = e0 + NT1, ec = e0 + 2 * NT1, ed = e0 + 3 * NT1;
            int sa, da, sb, db, sc, dc, sd, dd;
            if (is64) {
                sa = ei[2 * ea]; da = ei[2 * E + 2 * ea];
                sb = ei[2 * eb]; db = ei[2 * E + 2 * eb];
                sc = ei[2 * ec]; dc = ei[2 * E + 2 * ec];
                sd = ei[2 * ed]; dd = ei[2 * E + 2 * ed];
            } else {
                sa = ei[ea]; da = ei[E + ea];
                sb = ei[eb]; db = ei[E + eb];
                sc = ei[ec]; dc = ei[E + ec];
                sd = ei[ed]; dd = ei[E + ed];
            }
            int qa = atomicAdd(&g_cur[da], 1);
            int qb = atomicAdd(&g_cur[db], 1);
            int qc = atomicAdd(&g_cur[dc], 1);
            int qd = atomicAdd(&g_cur[dd], 1);
            int2 pa; pa.x = sa; pa.y = __float_as_int(g_dinv[sa] * g_dinv[da]);
            int2 pb; pb.x = sb; pb.y = __float_as_int(g_dinv[sb] * g_dinv[db]);
            int2 pc; pc.x = sc; pc.y = __float_as_int(g_dinv[sc] * g_dinv[dc]);
            int2 pd; pd.x = sd; pd.y = __float_as_int(g_dinv[sd] * g_dinv[dd]);
            g_csr[qa] = pa;
            g_csr[qb] = pb;
            g_csr[qc] = pc;
            g_csr[qd] = pd;
        }
        for (; e0 < E; e0 += NT1) {
            int s, d;
            if (is64) { s = ei[2 * e0]; d = ei[2 * E + 2 * e0]; }
            else      { s = ei[e0];     d = ei[E + e0]; }
            int slot = atomicAdd(&g_cur[d], 1);
            int2 p; p.x = s; p.y = __float_as_int(g_dinv[s] * g_dinv[d]);
            g_csr[slot] = p;
        }
    }
}

// ==================== GEMM1: h1 = x @ W1 -> fp16 store ====================
__global__ __launch_bounds__(128) void k_gemm1(const float* __restrict__ x,
                                               const float* __restrict__ W,
                                               int n) {
    __shared__ float ws[32][128];
    __shared__ float xs[32][68];
    int tid = threadIdx.x;
    int row0 = blockIdx.x * 64;
    int tr = tid >> 4;
    int tc = tid & 15;
    unsigned long long acc[8][4];
#pragma unroll
    for (int r = 0; r < 8; ++r)
#pragma unroll
        for (int j = 0; j < 4; ++j) acc[r][j] = 0ull;

    for (int kc = 0; kc < 4; ++kc) {
        __syncthreads();
        for (int i = tid * 4; i < 32 * 128; i += 128 * 4)
            *(float4*)(&ws[0][0] + i) = *(const float4*)(W + kc * 32 * 128 + i);
        for (int i = tid; i < 64 * 32; i += 128) {
            int r = i >> 5, k = i & 31;
            int gr = row0 + r;
            xs[k][r] = (gr < n) ? x[(size_t)gr * 128 + kc * 32 + k] : 0.0f;
        }
        __syncthreads();
#pragma unroll 4
        for (int k = 0; k < 32; ++k) {
            float4 xa = *(const float4*)&xs[k][tr * 8];
            float4 xb = *(const float4*)&xs[k][tr * 8 + 4];
            float4 wa = *(const float4*)&ws[k][tc * 8];
            float4 wb = *(const float4*)&ws[k][tc * 8 + 4];
            unsigned long long wp[4] = { pk2(wa.x, wa.y), pk2(wa.z, wa.w),
                                         pk2(wb.x, wb.y), pk2(wb.z, wb.w) };
            unsigned long long xd[8] = { pk2(xa.x, xa.x), pk2(xa.y, xa.y),
                                         pk2(xa.z, xa.z), pk2(xa.w, xa.w),
                                         pk2(xb.x, xb.x), pk2(xb.y, xb.y),
                                         pk2(xb.z, xb.z), pk2(xb.w, xb.w) };
#pragma unroll
            for (int r = 0; r < 8; ++r)
#pragma unroll
                for (int j = 0; j < 4; ++j)
                    acc[r][j] = ffma2(xd[r], wp[j], acc[r][j]);
        }
    }
#pragma unroll
    for (int r = 0; r < 8; ++r) {
        int gr = row0 + tr * 8 + r;
        if (gr >= n) continue;
        float2 p0 = up2(acc[r][0]), p1 = up2(acc[r][1]);
        float2 p2 = up2(acc[r][2]), p3 = up2(acc[r][3]);
        __half2 h[4] = { __float22half2_rn(p0), __float22half2_rn(p1),
                         __float22half2_rn(p2), __float22half2_rn(p3) };
        *(uint4*)(g_h1 + (size_t)gr * 128 + tc * 8) = *(const uint4*)h;
    }
}

// ==================== fused gathers (R7 proven): L1+relu+GEMM2 -> bar -> L2+lsm ====================
__device__ __forceinline__ void fma8(float* a, uint4 u, float w) {
    __half2* h = (__half2*)&u;
#pragma unroll
    for (int j = 0; j < 4; ++j) {
        float2 f = __half22float2(h[j]);
        a[2 * j]     += f.x * w;
        a[2 * j + 1] += f.y * w;
    }
}

__global__ __launch_bounds__(256, 4) void k_gather(float* __restrict__ out,
                                                   const float* __restrict__ b1,
                                                   const float* __restrict__ W2,
                                                   const float* __restrict__ b2,
                                                   int n) {
    __shared__ float w2s[128 * 16];      // row-major [k][c]
    __shared__ float rows[8][2][132];    // per warp, per half-warp node row (padded)
    int tid = threadIdx.x;
    for (int i = tid; i < 2048; i += 256) w2s[i] = W2[i];
    __syncthreads();

    int warp = tid >> 5, lane = tid & 31;
    int half = lane >> 4, hl = lane & 15;
    int c = hl << 3;                     // 8 halfs (16 B) per lane
    int npair = (n + 1) >> 1;

    // ---- layer 1: half-warp per node (persistent), fused relu + GEMM2 ----
    for (int pair = blockIdx.x * 8 + warp; pair < npair; pair += NB2 * 8) {
        int node = pair * 2 + half;
        if (node < n) {
            float a[8];
            float di = g_dinv[node];
            float w0 = di * di;
            uint4 u = *(const uint4*)(g_h1 + (size_t)node * 128 + c);
            {
                __half2* h = (__half2*)&u;
#pragma unroll
                for (int j = 0; j < 4; ++j) {
                    float2 f = __half22float2(h[j]);
                    a[2 * j]     = f.x * w0;
                    a[2 * j + 1] = f.y * w0;
                }
            }
            int e = g_off[node], e1 = g_off[node + 1];
            for (; e + 4 <= e1; e += 4) {
                int2 p0 = g_csr[e],     p1 = g_csr[e + 1];
                int2 p2 = g_csr[e + 2], p3 = g_csr[e + 3];
                uint4 u0 = *(const uint4*)(g_h1 + (size_t)p0.x * 128 + c);
                uint4 u1 = *(const uint4*)(g_h1 + (size_t)p1.x * 128 + c);
                uint4 u2 = *(const uint4*)(g_h1 + (size_t)p2.x * 128 + c);
                uint4 u3 = *(const uint4*)(g_h1 + (size_t)p3.x * 128 + c);
                fma8(a, u0, __int_as_float(p0.y));
                fma8(a, u1, __int_as_float(p1.y));
                fma8(a, u2, __int_as_float(p2.y));
                fma8(a, u3, __int_as_float(p3.y));
            }
            for (; e < e1; ++e) {
                int2 p = g_csr[e];
                uint4 uu = *(const uint4*)(g_h1 + (size_t)p.x * 128 + c);
                fma8(a, uu, __int_as_float(p.y));
            }
            float4 ba = *(const float4*)(b1 + c);
            float4 bb = *(const float4*)(b1 + c + 4);
            float* rw = &rows[warp][half][c];
            rw[0] = fmaxf(a[0] + ba.x, 0.0f);
            rw[1] = fmaxf(a[1] + ba.y, 0.0f);
            rw[2] = fmaxf(a[2] + ba.z, 0.0f);
            rw[3] = fmaxf(a[3] + ba.w, 0.0f);
            rw[4] = fmaxf(a[4] + bb.x, 0.0f);
            rw[5] = fmaxf(a[5] + bb.y, 0.0f);
            rw[6] = fmaxf(a[6] + bb.z, 0.0f);
            rw[7] = fmaxf(a[7] + bb.w, 0.0f);
        }
        __syncwarp();
        // fused GEMM2: each half-warp's 16 lanes produce its node's 16 outputs
        int gnode = pair * 2 + half;
        if (gnode < n) {
            const float* rr = &rows[warp][half][0];
            float s = 0.0f;
#pragma unroll 8
            for (int k = 0; k < 128; k += 4) {
                float4 r = *(const float4*)(rr + k);
                s += r.x * w2s[(k + 0) * 16 + hl];
                s += r.y * w2s[(k + 1) * 16 + hl];
                s += r.z * w2s[(k + 2) * 16 + hl];
                s += r.w * w2s[(k + 3) * 16 + hl];
            }
            g_h2[(size_t)gnode * 16 + hl] = s;
        }
        __syncwarp();
    }

    gbar(1, NB2);

    // ---- layer 2: 4 lanes per node (persistent) + b2 + log_softmax ----
    for (int idx = blockIdx.x * 256 + tid; idx < n * 4; idx += NB2 * 256) {
        int node = idx >> 2;
        int q = (idx & 3) << 2;
        float di = g_dinv[node];
        float w0 = di * di;
        float4 acc = *(const float4*)(g_h2 + (size_t)node * 16 + q);
        acc.x *= w0; acc.y *= w0; acc.z *= w0; acc.w *= w0;
        int e = g_off[node], e1 = g_off[node + 1];
        for (; e + 4 <= e1; e += 4) {
            int2 p0 = g_csr[e],     p1 = g_csr[e + 1];
            int2 p2 = g_csr[e + 2], p3 = g_csr[e + 3];
            float4 v0 = *(const float4*)(g_h2 + (size_t)p0.x * 16 + q);
            float4 v1 = *(const float4*)(g_h2 + (size_t)p1.x * 16 + q);
            float4 v2 = *(const float4*)(g_h2 + (size_t)p2.x * 16 + q);
            float4 v3 = *(const float4*)(g_h2 + (size_t)p3.x * 16 + q);
            float w0_ = __int_as_float(p0.y), w1_ = __int_as_float(p1.y);
            float w2_ = __int_as_float(p2.y), w3_ = __int_as_float(p3.y);
            acc.x += v0.x * w0_ + v1.x * w1_ + v2.x * w2_ + v3.x * w3_;
            acc.y += v0.y * w0_ + v1.y * w1_ + v2.y * w2_ + v3.y * w3_;
            acc.z += v0.z * w0_ + v1.z * w1_ + v2.z * w2_ + v3.z * w3_;
            acc.w += v0.w * w0_ + v1.w * w1_ + v2.w * w2_ + v3.w * w3_;
        }
        for (; e < e1; ++e) {
            int2 p = g_csr[e];
            float wt = __int_as_float(p.y);
            float4 v = *(const float4*)(g_h2 + (size_t)p.x * 16 + q);
            acc.x += v.x * wt; acc.y += v.y * wt; acc.z += v.z * wt; acc.w += v.w * wt;
        }
        float4 b = *(const float4*)(b2 + q);
        float4 v = make_float4(acc.x + b.x, acc.y + b.y, acc.z + b.z, acc.w + b.w);
        float m = fmaxf(fmaxf(v.x, v.y), fmaxf(v.z, v.w));
        m = fmaxf(m, __shfl_xor_sync(0xffffffffu, m, 1, 4));
        m = fmaxf(m, __shfl_xor_sync(0xffffffffu, m, 2, 4));
        float s4 = expf(v.x - m) + expf(v.y - m) + expf(v.z - m) + expf(v.w - m);
        s4 += __shfl_xor_sync(0xffffffffu, s4, 1, 4);
        s4 += __shfl_xor_sync(0xffffffffu, s4, 2, 4);
        float L = m + logf(s4);
        *(float4*)(out + (size_t)node * 16 + q) =
            make_float4(v.x - L, v.y - L, v.z - L, v.w - L);
    }
}

// ---------------- launch: fork/join, fused build || gemm1, then fused gather ----------------
extern "C" void kernel_launch(void* const* d_in, const int* in_sizes, int n_in,
                              void* d_out, int out_size) {
    const float* x  = (const float*)d_in[0];
    const int*   ei = (const int*)d_in[1];
    const float* W1 = (const float*)d_in[2];
    const float* b1 = (const float*)d_in[3];
    const float* W2 = (const float*)d_in[4];
    const float* b2 = (const float*)d_in[5];
    float* out = (float*)d_out;

    int n = in_sizes[0] / 128;
    int E = in_sizes[1] / 2;

    static cudaStream_t s1 = nullptr, s2 = nullptr;
    static cudaEvent_t ev0 = nullptr, ev1 = nullptr, ev2 = nullptr;
    if (!s1) {
        cudaStreamCreateWithFlags(&s1, cudaStreamNonBlocking);
        cudaStreamCreateWithFlags(&s2, cudaStreamNonBlocking);
        cudaEventCreateWithFlags(&ev0, cudaEventDisableTiming);
        cudaEventCreateWithFlags(&ev1, cudaEventDisableTiming);
        cudaEventCreateWithFlags(&ev2, cudaEventDisableTiming);
    }

    cudaEventRecord(ev0, 0);
    cudaStreamWaitEvent(s1, ev0, 0);
    cudaStreamWaitEvent(s2, ev0, 0);

    k_build<<<NB1, BT1, 0, s1>>>(ei, n, E);
    cudaEventRecord(ev1, s1);

    k_gemm1<<<(n + 63) / 64, 128, 0, s2>>>(x, W1, n);
    cudaEventRecord(ev2, s2);

    cudaStreamWaitEvent(0, ev1, 0);
    cudaStreamWaitEvent(0, ev2, 0);

    k_gather<<<NB2, 256>>>(out, b1, W2, b2, n);
}